// round 2
// baseline (speedup 1.0000x reference)
#include <cuda_runtime.h>

#define D 64
#define MAXN 20000
#define MAXE 320000
#define STEP 0.01f
#define NLAYERS 10

// ---------------- device scratch (static, no allocation) ----------------
__device__ float g_u[2][MAXN * D];   // mix(u) double buffer
__device__ float g_y[MAXN * D];      // current y (persistent across layers)
__device__ float g_ny[MAXN * D];     // mix(y) output
__device__ float g_ts[MAXN * D];     // (u - step*y) * inv_deg   (pre-scaled gather source)
__device__ float g_ys[MAXN * D];     // y * inv_deg
__device__ float g_gprev[MAXN * D];  // grad(x0) cache == g1 of previous layer
__device__ float g_invdeg[MAXN];
__device__ float g_v[2][MAXN];
__device__ float g_vs[MAXN];
__device__ int   g_cnts[MAXN];       // out-degree counts (src)
__device__ int   g_cntd[MAXN];       // in-degree counts (dst) for CSR
__device__ int   g_rowstart[MAXN + 1];
__device__ int   g_cursor[MAXN];
__device__ int   g_srcidx[MAXE];     // CSR by dst: source node per incoming edge

// ---------------- setup kernels ----------------
__global__ void k_init(int N) {
    int i = blockIdx.x * blockDim.x + threadIdx.x;
    if (i < N) { g_cnts[i] = 0; g_cntd[i] = 0; g_v[0][i] = 1.0f; }
}

__global__ void k_count(const int* __restrict__ src,
                        const int* __restrict__ dst, int E) {
    int e = blockIdx.x * blockDim.x + threadIdx.x;
    if (e < E) {
        atomicAdd(&g_cnts[src[e]], 1);
        atomicAdd(&g_cntd[dst[e]], 1);
    }
}

__global__ void k_invdeg(int N) {
    int i = blockIdx.x * blockDim.x + threadIdx.x;
    if (i < N) g_invdeg[i] = 1.0f / (1.0f + (float)g_cnts[i]);
}

// single-block exclusive scan of g_cntd -> g_rowstart / g_cursor
__global__ void k_scan(int N) {
    __shared__ int part[1024];
    int tid = threadIdx.x;
    int chunk = (N + 1023) >> 10;
    int begin = tid * chunk;
    int end = min(begin + chunk, N);
    int s = 0;
    for (int i = begin; i < end; i++) s += g_cntd[i];
    part[tid] = s;
    __syncthreads();
    for (int off = 1; off < 1024; off <<= 1) {
        int v = 0;
        if (tid >= off) v = part[tid - off];
        __syncthreads();
        part[tid] += v;
        __syncthreads();
    }
    int excl = tid ? part[tid - 1] : 0;
    for (int i = begin; i < end; i++) {
        g_rowstart[i] = excl;
        g_cursor[i]   = excl;
        excl += g_cntd[i];
    }
    if (tid == 1023) g_rowstart[N] = excl;
}

__global__ void k_fill(const int* __restrict__ src,
                       const int* __restrict__ dst, int E) {
    int e = blockIdx.x * blockDim.x + threadIdx.x;
    if (e < E) {
        int d = dst[e];
        int pos = atomicAdd(&g_cursor[d], 1);
        g_srcidx[pos] = src[e];
    }
}

// y0 = grad(x) = 2*A_n x_n + b_n ; also gprev = y0 (since x0 = x)
// 256 threads = 4 nodes per block
__global__ void k_grad_init(const float* __restrict__ A,
                            const float* __restrict__ b,
                            const float* __restrict__ x, int N) {
    __shared__ float xs[4][D];
    int local = threadIdx.x >> 6;     // node within block (0..3)
    int r = threadIdx.x & 63;         // row within node
    int n = blockIdx.x * 4 + local;
    if (n >= N) return;
    xs[local][r] = x[n * D + r];
    __syncwarp();
    // rows of one node span 2 warps; need both warps' xs -> syncthreads
    __syncthreads();
    const float* Ar = A + ((size_t)n * D + r) * D;
    float acc = 0.0f;
#pragma unroll
    for (int j = 0; j < D; j += 4) {
        float4 a = *(const float4*)(Ar + j);
        acc += a.x * xs[local][j] + a.y * xs[local][j + 1]
             + a.z * xs[local][j + 2] + a.w * xs[local][j + 3];
    }
    float g = 2.0f * acc + b[n * D + r];
    g_y[n * D + r] = g;
    g_gprev[n * D + r] = g;
}

// ---------------- per-layer kernels ----------------
// ts = (u - step*y)*inv_deg ; ys = y*inv_deg ; vs = v*inv_deg
__global__ void k_prep(const float* __restrict__ u_ext, int use_ext,
                       int usel, int vsel, int N) {
    int idx = blockIdx.x * blockDim.x + threadIdx.x;
    if (idx >= N * D) return;
    int n = idx >> 6;
    float id = g_invdeg[n];
    float uv = use_ext ? u_ext[idx] : g_u[usel][idx];
    float yv = g_y[idx];
    g_ts[idx] = (uv - STEP * yv) * id;
    g_ys[idx] = yv * id;
    if ((idx & 63) == 0) g_vs[n] = g_v[vsel][n] * id;
}

// segment-sum (gather form via CSR): newu = self + sum_in ts[src], newy likewise, newv scalar
__global__ void k_mix(int uout, int vout, int N) {
    int n = blockIdx.x;
    int f = threadIdx.x;
    float au = g_ts[n * D + f];
    float ay = g_ys[n * D + f];
    float av = (f == 0) ? g_vs[n] : 0.0f;
    int rs = g_rowstart[n], re = g_rowstart[n + 1];
    for (int k = rs; k < re; k++) {
        int s = g_srcidx[k];
        au += g_ts[s * D + f];
        ay += g_ys[s * D + f];
        if (f == 0) av += g_vs[s];
    }
    g_u[uout][n * D + f] = au;
    g_ny[n * D + f] = ay;
    if (f == 0) g_v[vout][n] = av;
}

// x1 = newu/newv ; g1 = 2*A x1 + b ; y = newy + g1 - gprev ; gprev = g1 ; out = x1
// 256 threads = 4 nodes per block
__global__ void k_finish(const float* __restrict__ A,
                         const float* __restrict__ b,
                         float* __restrict__ out,
                         int uout, int vout, int N) {
    __shared__ float xs[4][D];
    int local = threadIdx.x >> 6;
    int r = threadIdx.x & 63;
    int n = blockIdx.x * 4 + local;
    if (n >= N) return;
    float invv = 1.0f / g_v[vout][n];
    float x1 = g_u[uout][n * D + r] * invv;
    xs[local][r] = x1;
    out[n * D + r] = x1;
    __syncthreads();
    const float* Ar = A + ((size_t)n * D + r) * D;
    float acc = 0.0f;
#pragma unroll
    for (int j = 0; j < D; j += 4) {
        float4 a = *(const float4*)(Ar + j);
        acc += a.x * xs[local][j] + a.y * xs[local][j + 1]
             + a.z * xs[local][j + 2] + a.w * xs[local][j + 3];
    }
    float g1 = 2.0f * acc + b[n * D + r];
    g_y[n * D + r] = g_ny[n * D + r] + g1 - g_gprev[n * D + r];
    g_gprev[n * D + r] = g1;
}

__global__ void k_tail(float* out, int base, int extra, long long comm) {
    if (threadIdx.x == 0) {
        if (extra == 1) out[base] = (float)comm;
        else if (extra >= 2) *(long long*)(out + base) = comm;
    }
}

// ---------------- launch ----------------
extern "C" void kernel_launch(void* const* d_in, const int* in_sizes, int n_in,
                              void* d_out, int out_size) {
    const float* A = (const float*)d_in[0];
    const float* b = (const float*)d_in[1];
    const float* x = (const float*)d_in[2];
    const int* ei = (const int*)d_in[3];
    int N = in_sizes[1] / D;
    int E = in_sizes[3] / 2;
    const int* src = ei;
    const int* dst = ei + E;
    float* out = (float*)d_out;

    const int TB = 256;
    k_init<<<(N + TB - 1) / TB, TB>>>(N);
    k_count<<<(E + TB - 1) / TB, TB>>>(src, dst, E);
    k_invdeg<<<(N + TB - 1) / TB, TB>>>(N);
    k_scan<<<1, 1024>>>(N);
    k_fill<<<(E + TB - 1) / TB, TB>>>(src, dst, E);
    k_grad_init<<<(N + 3) / 4, 256>>>(A, b, x, N);

    for (int l = 0; l < NLAYERS; l++) {
        int uin  = (l + 1) & 1;   // unused when l==0
        int uout = l & 1;
        int vin  = l & 1;
        int vout = (l + 1) & 1;
        k_prep<<<(N * D + TB - 1) / TB, TB>>>(x, (l == 0) ? 1 : 0, uin, vin, N);
        k_mix<<<N, D>>>(uout, vout, N);
        k_finish<<<(N + 3) / 4, 256>>>(A, b, out, uout, vout, N);
    }

    int extra = out_size - N * D;
    if (extra > 0) k_tail<<<1, 32>>>(out, N * D, extra, (long long)(3 * NLAYERS) * E);
}

// round 3
// speedup vs baseline: 1.0850x; 1.0850x over previous
#include <cuda_runtime.h>

#define D 64
#define MAXN 20000
#define MAXE 320000
#define STEP 0.01f
#define NLAYERS 10
#define SCB 256

// ---------------- device scratch ----------------
// per-node interleaved [ts(64) | ys(64)], double buffered
__device__ float g_tsys[2][MAXN * 128];
__device__ float g_vs[2][MAXN];
__device__ float g_gprev[MAXN * D];
__device__ float g_invdeg[MAXN];
__device__ int   g_cnts[MAXN];
__device__ int   g_cntd[MAXN];
__device__ int   g_partial[128];
__device__ int   g_rowstart[MAXN + 1];
__device__ int   g_cursor[MAXN];
__device__ int   g_srcidx[MAXE];

// ---------------- setup ----------------
__global__ void k_init(int N) {
    int i = blockIdx.x * blockDim.x + threadIdx.x;
    if (i < N) { g_cnts[i] = 0; g_cntd[i] = 0; }
}

__global__ void k_count(const int* __restrict__ src,
                        const int* __restrict__ dst, int E) {
    int e = blockIdx.x * blockDim.x + threadIdx.x;
    if (e < E) {
        atomicAdd(&g_cnts[src[e]], 1);
        atomicAdd(&g_cntd[dst[e]], 1);
    }
}

__global__ void k_invdeg(int N) {
    int i = blockIdx.x * blockDim.x + threadIdx.x;
    if (i < N) g_invdeg[i] = 1.0f / (1.0f + (float)g_cnts[i]);
}

// block partial sums of g_cntd
__global__ void k_partial_sum(int N) {
    __shared__ int s[SCB];
    int i = blockIdx.x * SCB + threadIdx.x;
    s[threadIdx.x] = (i < N) ? g_cntd[i] : 0;
    __syncthreads();
    for (int o = SCB / 2; o > 0; o >>= 1) {
        if (threadIdx.x < o) s[threadIdx.x] += s[threadIdx.x + o];
        __syncthreads();
    }
    if (threadIdx.x == 0) g_partial[blockIdx.x] = s[0];
}

// exclusive scan of partials (nb <= 128), single block of 128
__global__ void k_scan_partials(int nb, int N, int E) {
    __shared__ int s[128];
    int t = threadIdx.x;
    int v = (t < nb) ? g_partial[t] : 0;
    s[t] = v;
    __syncthreads();
    for (int o = 1; o < 128; o <<= 1) {
        int a = (t >= o) ? s[t - o] : 0;
        __syncthreads();
        s[t] += a;
        __syncthreads();
    }
    if (t < nb) g_partial[t] = s[t] - v;   // exclusive
    if (t == 0) g_rowstart[N] = E;
}

__global__ void k_rowfill(int N) {
    __shared__ int s[SCB];
    int i = blockIdx.x * SCB + threadIdx.x;
    int c = (i < N) ? g_cntd[i] : 0;
    s[threadIdx.x] = c;
    __syncthreads();
    for (int o = 1; o < SCB; o <<= 1) {
        int a = (threadIdx.x >= o) ? s[threadIdx.x - o] : 0;
        __syncthreads();
        s[threadIdx.x] += a;
        __syncthreads();
    }
    if (i < N) {
        int excl = s[threadIdx.x] - c + g_partial[blockIdx.x];
        g_rowstart[i] = excl;
        g_cursor[i]   = excl;
    }
}

__global__ void k_fill(const int* __restrict__ src,
                       const int* __restrict__ dst, int E) {
    int e = blockIdx.x * blockDim.x + threadIdx.x;
    if (e < E) {
        int pos = atomicAdd(&g_cursor[dst[e]], 1);
        g_srcidx[pos] = src[e];
    }
}

// g0 = 2*A x + b; gprev = g0; ts = (x - step*g0)*invdeg; ys = g0*invdeg; vs = invdeg
__global__ void k_grad_init(const float* __restrict__ A,
                            const float* __restrict__ b,
                            const float* __restrict__ x, int N) {
    __shared__ float xs[4][D];
    int local = threadIdx.x >> 6;
    int r = threadIdx.x & 63;
    int n = blockIdx.x * 4 + local;
    bool ok = (n < N);
    int nc = ok ? n : (N - 1);
    xs[local][r] = x[nc * D + r];
    __syncthreads();
    const float4* Ar = (const float4*)(A + ((size_t)nc * D + r) * D);
    float acc = 0.0f;
#pragma unroll
    for (int j = 0; j < 16; j++) {
        float4 a = __ldcs(Ar + j);
        acc += a.x * xs[local][j * 4] + a.y * xs[local][j * 4 + 1]
             + a.z * xs[local][j * 4 + 2] + a.w * xs[local][j * 4 + 3];
    }
    if (!ok) return;
    float g = 2.0f * acc + b[n * D + r];
    float id = g_invdeg[n];
    g_gprev[n * D + r] = g;
    g_tsys[0][n * 128 + r]      = (xs[local][r] - STEP * g) * id;
    g_tsys[0][n * 128 + 64 + r] = g * id;
    if (r == 0) g_vs[0][n] = id;
}

// ---------------- fused per-layer kernel ----------------
// gather (mix) -> x1 = u/v -> g1 = 2*A x1 + b -> y = ny + g1 - gprev -> write next sources
__global__ void k_layer(const float* __restrict__ A,
                        const float* __restrict__ b,
                        float* __restrict__ out,
                        int ib, int ob, int last, int N) {
    __shared__ float sh[4][128];
    __shared__ float shv[4];
    int local = threadIdx.x >> 6;   // node in block
    int t = threadIdx.x & 63;
    int lane = t & 31;
    int n = blockIdx.x * 4 + local;
    bool ok = (n < N);
    int nc = ok ? n : (N - 1);

    const float2* tin = (const float2*)g_tsys[ib];
    const float* vin = g_vs[ib];

    int rs = g_rowstart[nc];
    int re = g_rowstart[nc + 1];
    float2 acc = tin[nc * 64 + t];          // self term (already scaled)
    float vacc = (t == 0) ? vin[nc] : 0.0f;

    for (int base = rs; base < re; base += 32) {
        int k = base + lane;
        int myidx = (k < re) ? g_srcidx[k] : 0;
        int m = min(32, re - base);
        for (int j = 0; j < m; j++) {
            int s = __shfl_sync(0xffffffffu, myidx, j);
            float2 vv = tin[s * 64 + t];
            acc.x += vv.x;
            acc.y += vv.y;
            if (t == 0) vacc += vin[s];
        }
    }

    sh[local][2 * t]     = acc.x;   // floats [0..63]=u_new, [64..127]=ny
    sh[local][2 * t + 1] = acc.y;
    if (t == 0) shv[local] = vacc;
    __syncthreads();

    float u_r  = sh[local][t];
    float ny_r = sh[local][64 + t];
    float invv = 1.0f / shv[local];
    float x1 = u_r * invv;
    sh[local][t] = x1;              // own-slot overwrite, no race
    __syncthreads();

    const float4* Ar = (const float4*)(A + ((size_t)nc * D + t) * D);
    float accg = 0.0f;
#pragma unroll
    for (int j = 0; j < 16; j++) {
        float4 a = __ldcs(Ar + j);
        accg += a.x * sh[local][j * 4] + a.y * sh[local][j * 4 + 1]
              + a.z * sh[local][j * 4 + 2] + a.w * sh[local][j * 4 + 3];
    }
    if (!ok) return;

    float g1 = 2.0f * accg + b[n * D + t];
    float ynew = ny_r + g1 - g_gprev[n * D + t];
    g_gprev[n * D + t] = g1;

    if (last) {
        out[n * D + t] = x1;
    } else {
        float id = g_invdeg[n];
        g_tsys[ob][n * 128 + t]      = (u_r - STEP * ynew) * id;
        g_tsys[ob][n * 128 + 64 + t] = ynew * id;
        if (t == 0) g_vs[ob][n] = shv[local] * id;
    }
}

__global__ void k_tail(float* out, int base, int extra, long long comm) {
    if (threadIdx.x == 0) {
        if (extra == 1) out[base] = (float)comm;
        else if (extra >= 2) *(long long*)(out + base) = comm;
    }
}

// ---------------- launch ----------------
extern "C" void kernel_launch(void* const* d_in, const int* in_sizes, int n_in,
                              void* d_out, int out_size) {
    const float* A = (const float*)d_in[0];
    const float* b = (const float*)d_in[1];
    const float* x = (const float*)d_in[2];
    const int* ei = (const int*)d_in[3];
    int N = in_sizes[1] / D;
    int E = in_sizes[3] / 2;
    const int* src = ei;
    const int* dst = ei + E;
    float* out = (float*)d_out;

    const int TB = 256;
    int nb = (N + SCB - 1) / SCB;

    k_init<<<(N + TB - 1) / TB, TB>>>(N);
    k_count<<<(E + TB - 1) / TB, TB>>>(src, dst, E);
    k_invdeg<<<(N + TB - 1) / TB, TB>>>(N);
    k_partial_sum<<<nb, SCB>>>(N);
    k_scan_partials<<<1, 128>>>(nb, N, E);
    k_rowfill<<<nb, SCB>>>(N);
    k_fill<<<(E + TB - 1) / TB, TB>>>(src, dst, E);
    k_grad_init<<<(N + 3) / 4, 256>>>(A, b, x, N);

    int blocks = (N + 3) / 4;
    for (int l = 0; l < NLAYERS; l++) {
        int ib = l & 1;
        int ob = (l + 1) & 1;
        k_layer<<<blocks, 256>>>(A, b, out, ib, ob, (l == NLAYERS - 1) ? 1 : 0, N);
    }

    int extra = out_size - N * D;
    if (extra > 0) k_tail<<<1, 32>>>(out, N * D, extra, (long long)(3 * NLAYERS) * E);
}

// round 5
// speedup vs baseline: 1.1289x; 1.0405x over previous
#include <cuda_runtime.h>

#define D 64
#define MAXN 20000
#define MAXE 320000
#define STEP 0.01f
#define NLAYERS 10
#define SCB 256
#define PADW 68   // padded row stride (floats) for conflict-free LDS.128

// ---------------- device scratch ----------------
__device__ float g_tsys[2][MAXN * 128];   // per-node [ts(64)|ys(64)], double buffered
__device__ float g_vs[2][MAXN];
__device__ float g_gprev[MAXN * D];
__device__ float g_invdeg[MAXN];
__device__ int   g_cnts[MAXN];            // zero-init at load; re-zeroed by cleanup
__device__ int   g_cntd[MAXN];
__device__ int   g_partial[128];
__device__ int   g_rowstart[MAXN + 1];
__device__ int   g_cursor[MAXN];
__device__ int   g_srcidx[MAXE];

// ---------------- cp.async helpers ----------------
__device__ __forceinline__ void cp_async16(void* smem, const void* gmem) {
    unsigned s = (unsigned)__cvta_generic_to_shared(smem);
    asm volatile("cp.async.cg.shared.global [%0], [%1], 16;\n" :: "r"(s), "l"(gmem));
}
__device__ __forceinline__ void cp_commit() { asm volatile("cp.async.commit_group;\n"); }
__device__ __forceinline__ void cp_wait0()  { asm volatile("cp.async.wait_group 0;\n"); }

// ---------------- setup ----------------
__global__ void k_count(const int* __restrict__ src,
                        const int* __restrict__ dst, int E) {
    int e = blockIdx.x * blockDim.x + threadIdx.x;
    if (e < E) {
        atomicAdd(&g_cnts[src[e]], 1);
        atomicAdd(&g_cntd[dst[e]], 1);
    }
}

// invdeg + per-block partial sums of cntd (fused)
__global__ void k_prep_deg(int N) {
    __shared__ int s[SCB];
    int i = blockIdx.x * SCB + threadIdx.x;
    int c = 0;
    if (i < N) {
        g_invdeg[i] = 1.0f / (1.0f + (float)g_cnts[i]);
        c = g_cntd[i];
    }
    s[threadIdx.x] = c;
    __syncthreads();
    for (int o = SCB / 2; o > 0; o >>= 1) {
        if (threadIdx.x < o) s[threadIdx.x] += s[threadIdx.x + o];
        __syncthreads();
    }
    if (threadIdx.x == 0) g_partial[blockIdx.x] = s[0];
}

__global__ void k_scan_partials(int nb, int N, int E) {
    __shared__ int s[128];
    int t = threadIdx.x;
    int v = (t < nb) ? g_partial[t] : 0;
    s[t] = v;
    __syncthreads();
    for (int o = 1; o < 128; o <<= 1) {
        int a = (t >= o) ? s[t - o] : 0;
        __syncthreads();
        s[t] += a;
        __syncthreads();
    }
    if (t < nb) g_partial[t] = s[t] - v;   // exclusive
    if (t == 0) g_rowstart[N] = E;
}

__global__ void k_rowfill(int N) {
    __shared__ int s[SCB];
    int i = blockIdx.x * SCB + threadIdx.x;
    int c = (i < N) ? g_cntd[i] : 0;
    s[threadIdx.x] = c;
    __syncthreads();
    for (int o = 1; o < SCB; o <<= 1) {
        int a = (threadIdx.x >= o) ? s[threadIdx.x - o] : 0;
        __syncthreads();
        s[threadIdx.x] += a;
        __syncthreads();
    }
    if (i < N) {
        int excl = s[threadIdx.x] - c + g_partial[blockIdx.x];
        g_rowstart[i] = excl;
        g_cursor[i]   = excl;
    }
}

__global__ void k_fill(const int* __restrict__ src,
                       const int* __restrict__ dst, int E) {
    int e = blockIdx.x * blockDim.x + threadIdx.x;
    if (e < E) {
        int pos = atomicAdd(&g_cursor[dst[e]], 1);
        g_srcidx[pos] = src[e];
    }
}

// ---------------- grad_init: 2 nodes per 128-thread block, smem-staged A ----------------
// g0 = 2*A x + b; gprev = g0; ts = (x - step*g0)*invdeg; ys = g0*invdeg; vs = invdeg
__global__ void __launch_bounds__(128) k_grad_init(
        const float* __restrict__ A, const float* __restrict__ b,
        const float* __restrict__ x, int N) {
    __shared__ __align__(16) float tile[2][D * PADW];
    __shared__ __align__(16) float xs[2][D];
    int tid = threadIdx.x;
    int local = tid >> 6;
    int t = tid & 63;
    int n = blockIdx.x * 2 + local;
    bool ok = (n < N);
    int nc = ok ? n : (N - 1);

    // stage A tiles for both nodes (coalesced, register-free)
#pragma unroll
    for (int nd = 0; nd < 2; nd++) {
        int nn = min(blockIdx.x * 2 + nd, N - 1);
        const float* src = A + (size_t)nn * (D * D);
#pragma unroll
        for (int k = 0; k < 8; k++) {
            int q = k * 128 + tid;          // float4 index 0..1023
            int r = q >> 4;
            int c = (q & 15) * 4;
            cp_async16(&tile[nd][r * PADW + c], src + q * 4);
        }
    }
    cp_commit();

    xs[local][t] = x[nc * D + t];
    cp_wait0();
    __syncthreads();

    float acc = 0.0f;
#pragma unroll
    for (int j = 0; j < 16; j++) {
        float4 a  = *(const float4*)&tile[local][t * PADW + 4 * j];
        float4 xv = *(const float4*)&xs[local][4 * j];
        acc += a.x * xv.x + a.y * xv.y + a.z * xv.z + a.w * xv.w;
    }
    if (!ok) return;
    float g = 2.0f * acc + b[n * D + t];
    float id = g_invdeg[n];
    g_gprev[n * D + t] = g;
    g_tsys[0][n * 128 + t]      = (xs[local][t] - STEP * g) * id;
    g_tsys[0][n * 128 + 64 + t] = g * id;
    if (t == 0) g_vs[0][n] = id;
}

// ---------------- fused per-layer kernel: 2 nodes per 128-thread block ----------------
__global__ void __launch_bounds__(128) k_layer(
        const float* __restrict__ A, const float* __restrict__ b,
        float* __restrict__ out, int ib, int ob, int last, int N) {
    __shared__ __align__(16) float tile[2][D * PADW];
    __shared__ __align__(16) float sh[2][128];
    __shared__ float shv[2];
    int tid = threadIdx.x;
    int local = tid >> 6;
    int t = tid & 63;
    int lane = t & 31;
    int n = blockIdx.x * 2 + local;
    bool ok = (n < N);
    int nc = ok ? n : (N - 1);

    // 1) kick off A staging immediately (DRAM stream under gather latency)
#pragma unroll
    for (int nd = 0; nd < 2; nd++) {
        int nn = min(blockIdx.x * 2 + nd, N - 1);
        const float* src = A + (size_t)nn * (D * D);
#pragma unroll
        for (int k = 0; k < 8; k++) {
            int q = k * 128 + tid;
            int r = q >> 4;
            int c = (q & 15) * 4;
            cp_async16(&tile[nd][r * PADW + c], src + q * 4);
        }
    }
    cp_commit();

    // 2) gather (mix) from previous layer's pre-scaled sources (L2-resident)
    // float2 index t covers floats (2t, 2t+1) of the node's [ts|ys] record
    const float2* tin = (const float2*)g_tsys[ib];
    const float* vin = g_vs[ib];
    int rs = g_rowstart[nc];
    int re = g_rowstart[nc + 1];
    float2 acc = tin[nc * 64 + t];               // self term (already scaled)
    float vacc = (t == 0) ? vin[nc] : 0.0f;

    for (int base = rs; base < re; base += 32) {
        int k = base + lane;
        int myidx = (k < re) ? g_srcidx[k] : 0;
        int m = min(32, re - base);
        for (int j = 0; j < m; j++) {
            int s = __shfl_sync(0xffffffffu, myidx, j);
            float2 vv = tin[s * 64 + t];
            acc.x += vv.x;
            acc.y += vv.y;
            if (t == 0) vacc += vin[s];
        }
    }

    // reconstruct mixed record in original float layout:
    // sh[i] = mixed float at position i  ->  sh[0..63]=u_new, sh[64..127]=ny
    sh[local][2 * t]     = acc.x;
    sh[local][2 * t + 1] = acc.y;
    if (t == 0) shv[local] = vacc;
    __syncthreads();

    float u_r  = sh[local][t];
    float ny_r = sh[local][64 + t];
    float vnew = shv[local];
    float x1 = u_r / vnew;
    __syncthreads();              // everyone has read u/ny before overwrite
    sh[local][t] = x1;            // x vector for GEMV
    cp_wait0();
    __syncthreads();

    // 3) GEMV from smem tile (conflict-free LDS.128 + broadcast x)
    float accg = 0.0f;
#pragma unroll
    for (int j = 0; j < 16; j++) {
        float4 a  = *(const float4*)&tile[local][t * PADW + 4 * j];
        float4 xv = *(const float4*)&sh[local][4 * j];
        accg += a.x * xv.x + a.y * xv.y + a.z * xv.z + a.w * xv.w;
    }
    if (!ok) return;

    float g1 = 2.0f * accg + b[n * D + t];
    float ynew = ny_r + g1 - g_gprev[n * D + t];
    g_gprev[n * D + t] = g1;

    if (last) {
        out[n * D + t] = x1;
    } else {
        float id = g_invdeg[n];
        g_tsys[ob][n * 128 + t]      = (u_r - STEP * ynew) * id;
        g_tsys[ob][n * 128 + 64 + t] = ynew * id;
        if (t == 0) g_vs[ob][n] = vnew * id;
    }
}

// cleanup: re-zero counters for next graph replay + emit comm_cost tail
__global__ void k_cleanup(float* out, int base, int extra, long long comm, int N) {
    int i = blockIdx.x * blockDim.x + threadIdx.x;
    if (i < N) { g_cnts[i] = 0; g_cntd[i] = 0; }
    if (i == 0) {
        if (extra == 1) out[base] = (float)comm;
        else if (extra >= 2) *(long long*)(out + base) = comm;
    }
}

// ---------------- launch ----------------
extern "C" void kernel_launch(void* const* d_in, const int* in_sizes, int n_in,
                              void* d_out, int out_size) {
    const float* A = (const float*)d_in[0];
    const float* b = (const float*)d_in[1];
    const float* x = (const float*)d_in[2];
    const int* ei = (const int*)d_in[3];
    int N = in_sizes[1] / D;
    int E = in_sizes[3] / 2;
    const int* src = ei;
    const int* dst = ei + E;
    float* out = (float*)d_out;

    const int TB = 256;
    int nb = (N + SCB - 1) / SCB;

    k_count<<<(E + TB - 1) / TB, TB>>>(src, dst, E);           // 0
    k_prep_deg<<<nb, SCB>>>(N);                                 // 1
    k_scan_partials<<<1, 128>>>(nb, N, E);                      // 2
    k_grad_init<<<(N + 1) / 2, 128>>>(A, b, x, N);              // 3 (profiled)
    k_rowfill<<<nb, SCB>>>(N);                                  // 4
    k_fill<<<(E + TB - 1) / TB, TB>>>(src, dst, E);             // 5

    int blocks = (N + 1) / 2;
    for (int l = 0; l < NLAYERS; l++) {
        int ib = l & 1;
        int ob = (l + 1) & 1;
        k_layer<<<blocks, 128>>>(A, b, out, ib, ob, (l == NLAYERS - 1) ? 1 : 0, N);
    }

    int extra = out_size - N * D;
    k_cleanup<<<(N + TB - 1) / TB, TB>>>(out, N * D, extra < 0 ? 0 : extra,
                                         (long long)(3 * NLAYERS) * E, N);
}